// round 14
// baseline (speedup 1.0000x reference)
#include <cuda_runtime.h>
#include <cstdint>

// EmbeddingLSQ: out[t, d] = (idx[t]==0) ? 0 : round(clamp(W[d, idx[t]]/a, -8, 7))*a
// where idx[t] = argmax_v x[t, v]  (x is one-hot float32).
//
// Two independent halves (tokens [0,2048) and [2048,4096)), overlapped:
//   default: K1a ........ K1b ........ sort_b gather_b
//   s2:             sort_a gather_a
// Fork/join with events (created once, on the uncaptured correctness call).
// Each half: dual-row early-exit scan -> per-half histogram -> per-half
// counting sort -> warp-coalesced gather (all 16 W loads preloaded, MLP=16).
//
// Cross-call state: g_cnt halves zero at entry (zero-init first call,
// re-zeroed by their sort each call) -> graph replays do identical work.

#define VOCAB    32000
#define DIM      1024
#define TOKENS   4096
#define HALF     2048
#define NTHREADS 256
#define U4_PER_ROW (VOCAB / 4)          // 8000 uint4 per row
#define NBUCKETS 2000                   // idx>>4 buckets (64B vocab span)
#define NBUCKPAD 2048
#define GROUP    32                     // tokens per gather group

__device__ int g_idx[TOKENS];
__device__ __align__(16) int g_cnt[2][NBUCKPAD];   // zero at entry each call
__device__ int g_order[2][HALF];
__device__ int g_sidx[2][HALF];

// ---------------- K1: dual-row early-exit scan + fused per-half histogram ----------------
__global__ __launch_bounds__(NTHREADS)
void find_idx_kernel(const float* __restrict__ x, int half) {
    const int t0 = half * HALF + blockIdx.x * 2;
    __shared__ int s_idx[2];
    __shared__ int s_flag[2];
    if (threadIdx.x < 2) { s_idx[threadIdx.x] = 0; s_flag[threadIdx.x] = 0; }
    __syncthreads();

    const uint4* __restrict__ rowA =
        reinterpret_cast<const uint4*>(x + (size_t)t0 * VOCAB);
    const uint4* __restrict__ rowB =
        reinterpret_cast<const uint4*>(x + (size_t)(t0 + 1) * VOCAB);
    volatile int* vf = s_flag;

    for (int base = 0; base < 32; base += 2) {
        const int fA = vf[0];
        const int fB = vf[1];
        if (fA & fB) break;
        const int j0 = threadIdx.x + base * NTHREADS;
        const int j1 = j0 + NTHREADS;
        const bool p0 = (j0 < U4_PER_ROW);
        const bool p1 = (j1 < U4_PER_ROW);
        uint4 a0, a1, b0, b1;
        if (!fA) {                       // block-uniform predicate
            if (p0) a0 = rowA[j0];
            if (p1) a1 = rowA[j1];
        }
        if (!fB) {
            if (p0) b0 = rowB[j0];
            if (p1) b1 = rowB[j1];
        }
        if (!fA) {
            if (p0 && (a0.x | a0.y | a0.z | a0.w)) {
                s_idx[0] = j0 * 4 + (a0.x ? 0 : (a0.y ? 1 : (a0.z ? 2 : 3)));
                vf[0] = 1;               // unique writer (one-hot row)
            }
            if (p1 && (a1.x | a1.y | a1.z | a1.w)) {
                s_idx[0] = j1 * 4 + (a1.x ? 0 : (a1.y ? 1 : (a1.z ? 2 : 3)));
                vf[0] = 1;
            }
        }
        if (!fB) {
            if (p0 && (b0.x | b0.y | b0.z | b0.w)) {
                s_idx[1] = j0 * 4 + (b0.x ? 0 : (b0.y ? 1 : (b0.z ? 2 : 3)));
                vf[1] = 1;
            }
            if (p1 && (b1.x | b1.y | b1.z | b1.w)) {
                s_idx[1] = j1 * 4 + (b1.x ? 0 : (b1.y ? 1 : (b1.z ? 2 : 3)));
                vf[1] = 1;
            }
        }
    }
    __syncthreads();
    if (threadIdx.x < 2) {
        const int idx = s_idx[threadIdx.x];
        g_idx[t0 + threadIdx.x] = idx;
        atomicAdd(&g_cnt[half][idx >> 4], 1);
    }
}

// ---------------- K2: per-half counting sort (1024 thr, hierarchical scan) ----------------
__global__ __launch_bounds__(1024)
void sort_kernel(int half) {
    __shared__ int s_off[NBUCKPAD];
    __shared__ int s_wsum[32];
    const int tid  = threadIdx.x;
    const int warp = tid >> 5;
    const int lane = tid & 31;

    const int b2 = tid * 2;
    int2 c = *reinterpret_cast<const int2*>(&g_cnt[half][b2]);
    *reinterpret_cast<int2*>(&g_cnt[half][b2]) = make_int2(0, 0);  // re-zero

    const int tsum = c.x + c.y;
    int incl = tsum;
    #pragma unroll
    for (int o = 1; o < 32; o <<= 1) {
        int n = __shfl_up_sync(0xffffffffu, incl, o);
        if (lane >= o) incl += n;
    }
    if (lane == 31) s_wsum[warp] = incl;
    __syncthreads();
    if (warp == 0) {
        int wsv = s_wsum[lane];
        int wincl = wsv;
        #pragma unroll
        for (int o = 1; o < 32; o <<= 1) {
            int n = __shfl_up_sync(0xffffffffu, wincl, o);
            if (lane >= o) wincl += n;
        }
        s_wsum[lane] = wincl - wsv;
    }
    __syncthreads();
    const int tbase = s_wsum[warp] + (incl - tsum);
    s_off[b2]     = tbase;
    s_off[b2 + 1] = tbase + c.x;
    __syncthreads();

    #pragma unroll
    for (int k = 0; k < HALF / 1024; k++) {
        const int tl  = tid + k * 1024;          // local token id in half
        const int tt  = half * HALF + tl;
        const int idx = g_idx[tt];
        const int pos = atomicAdd(&s_off[idx >> 4], 1);
        g_order[half][pos] = tt;
        g_sidx[half][pos]  = idx;
    }
}

// ---------------- K3: warp-coalesced gather, preload-16 + LSQ + transpose ----------------
// grid = (HALF/GROUP=64, DIM/128=8); block = 256 (8 warps).
__global__ __launch_bounds__(NTHREADS)
void gather_lsq_kernel(const float* __restrict__ w,
                       const float* __restrict__ alpha,
                       float* __restrict__ out, int half) {
    __shared__ int   s_tok[GROUP];
    __shared__ int   s_ix[GROUP];
    __shared__ float tile[32][33];

    const int tid  = threadIdx.x;
    const int warp = tid >> 5;
    const int lane = tid & 31;
    const int gbase  = blockIdx.x * GROUP;
    const int dbase0 = blockIdx.y * 128;

    if (tid < GROUP) {
        s_tok[tid] = g_order[half][gbase + tid];
        s_ix[tid]  = g_sidx[half][gbase + tid];
    }
    __syncthreads();

    const float a = __ldg(alpha);
    const int   myidx = s_ix[lane];        // lane <-> sorted token (load phase)
    const bool  pad   = (myidx == 0);

    // Preload all 16 gathered values: MLP=16 per thread.
    float wv[16];
    #pragma unroll
    for (int c = 0; c < 4; c++)
        #pragma unroll
        for (int r = 0; r < 4; r++)
            wv[c * 4 + r] =
                __ldg(w + (size_t)(dbase0 + c * 32 + warp * 4 + r) * VOCAB + myidx);

    #pragma unroll
    for (int c = 0; c < 4; c++) {
        const int dbase = dbase0 + c * 32;
        #pragma unroll
        for (int r = 0; r < 4; r++) {
            float q = pad ? 0.0f
                          : rintf(fminf(fmaxf(wv[c * 4 + r] / a, -8.0f), 7.0f)) * a;
            tile[warp * 4 + r][lane] = q;
        }
        __syncthreads();
        #pragma unroll
        for (int r = 0; r < 4; r++) {
            const int tl = warp * 4 + r;
            const int t  = s_tok[tl];
            out[(size_t)t * DIM + dbase + lane] = tile[lane][tl];
        }
        __syncthreads();
    }
}

// ---------------- launch: two halves, fork/join overlap ----------------
static cudaStream_t s2_stream() {
    static cudaStream_t s = []() {
        cudaStream_t st;
        cudaStreamCreateWithFlags(&st, cudaStreamNonBlocking);
        return st;
    }();
    return s;
}
static cudaEvent_t ev_fork() {
    static cudaEvent_t e = []() {
        cudaEvent_t ev;
        cudaEventCreateWithFlags(&ev, cudaEventDisableTiming);
        return ev;
    }();
    return e;
}
static cudaEvent_t ev_join() {
    static cudaEvent_t e = []() {
        cudaEvent_t ev;
        cudaEventCreateWithFlags(&ev, cudaEventDisableTiming);
        return ev;
    }();
    return e;
}

extern "C" void kernel_launch(void* const* d_in, const int* in_sizes, int n_in,
                              void* d_out, int out_size) {
    const float* x     = (const float*)d_in[0];
    const float* w     = (const float*)d_in[1];
    const float* alpha = (const float*)d_in[2];
    float* out = (float*)d_out;

    cudaStream_t s2 = s2_stream();
    cudaEvent_t  eF = ev_fork();
    cudaEvent_t  eJ = ev_join();

    dim3 ggrid(HALF / GROUP, DIM / 128);

    // half A scan on default stream
    find_idx_kernel<<<HALF / 2, NTHREADS>>>(x, 0);
    cudaEventRecord(eF, 0);
    cudaStreamWaitEvent(s2, eF, 0);

    // half A sort+gather on s2, overlapped with half B scan on default
    sort_kernel<<<1, 1024, 0, s2>>>(0);
    gather_lsq_kernel<<<ggrid, NTHREADS, 0, s2>>>(w, alpha, out, 0);
    cudaEventRecord(eJ, s2);

    find_idx_kernel<<<HALF / 2, NTHREADS>>>(x, 1);
    sort_kernel<<<1, 1024>>>(1);
    gather_lsq_kernel<<<ggrid, NTHREADS>>>(w, alpha, out, 1);

    // join: default stream completion implies half A done too
    cudaStreamWaitEvent(0, eJ, 0);
}

// round 15
// speedup vs baseline: 1.0443x; 1.0443x over previous
#include <cuda_runtime.h>
#include <cstdint>

// EmbeddingLSQ: out[t, d] = (idx[t]==0) ? 0 : round(clamp(W[d, idx[t]]/a, -8, 7))*a
// where idx[t] = argmax_v x[t, v]  (x is one-hot float32).
//
// Pipeline (3 kernels, single stream — R10/R11/R14 showed all overlap tricks lose):
//  K1 find_idx : QUAD-ROW early-exit scan, grid=1024 (fully resident in one
//                wave -> all 4096 rows progress concurrently at ~1/2 the
//                per-row rate -> detection-overshoot bytes halve).
//                batch-1 per row, MLP/thread=4. Fused histogram.
//  K2 sort     : 1024-thread counting sort, hierarchical warp-shfl scan,
//                re-zeroes g_cnt for the next call.
//  K3 gather   : warp-coalesced gather over sorted tokens, all 16 W loads
//                preloaded (MLP=16), smem transpose, coalesced writes.
//
// Cross-call state: g_cnt zero at entry every call (zero-init first call,
// re-zeroed by K2) -> graph replays do identical work.

#define VOCAB    32000
#define DIM      1024
#define TOKENS   4096
#define NTHREADS 256
#define U4_PER_ROW (VOCAB / 4)          // 8000 uint4 per row
#define NBUCKETS 2000                   // idx>>4 buckets (64B vocab span)
#define NBUCKPAD 2048
#define GROUP    32                     // tokens per gather group
#define ROWS_PB  4                      // rows per block in K1

__device__ int g_idx[TOKENS];
__device__ __align__(16) int g_cnt[NBUCKPAD];   // zero at entry of every call
__device__ int g_order[TOKENS];
__device__ int g_sidx[TOKENS];

// ---------------- K1: quad-row early-exit scan + fused histogram ----------------
__global__ __launch_bounds__(NTHREADS, 8)
void find_idx_kernel(const float* __restrict__ x) {
    const int t0 = blockIdx.x * ROWS_PB;
    __shared__ int s_idx[ROWS_PB];
    __shared__ int s_flag[ROWS_PB];
    if (threadIdx.x < ROWS_PB) { s_idx[threadIdx.x] = 0; s_flag[threadIdx.x] = 0; }
    __syncthreads();

    const uint4* __restrict__ row0 = reinterpret_cast<const uint4*>(x + (size_t)(t0 + 0) * VOCAB);
    const uint4* __restrict__ row1 = reinterpret_cast<const uint4*>(x + (size_t)(t0 + 1) * VOCAB);
    const uint4* __restrict__ row2 = reinterpret_cast<const uint4*>(x + (size_t)(t0 + 2) * VOCAB);
    const uint4* __restrict__ row3 = reinterpret_cast<const uint4*>(x + (size_t)(t0 + 3) * VOCAB);
    volatile int* vf = s_flag;

    // batch-1 per row, 4 rows interleaved: MLP/thread=4, per-row in-flight=1.
    for (int base = 0; base < 32; base++) {
        const int f0 = vf[0], f1 = vf[1], f2 = vf[2], f3 = vf[3];
        if (f0 & f1 & f2 & f3) break;
        const int j = threadIdx.x + base * NTHREADS;
        const bool p = (j < U4_PER_ROW);
        uint4 v0, v1, v2, v3;
        if (!f0 && p) v0 = row0[j];        // block-uniform row predicates
        if (!f1 && p) v1 = row1[j];
        if (!f2 && p) v2 = row2[j];
        if (!f3 && p) v3 = row3[j];
        if (!f0 && p && (v0.x | v0.y | v0.z | v0.w)) {
            s_idx[0] = j * 4 + (v0.x ? 0 : (v0.y ? 1 : (v0.z ? 2 : 3)));
            vf[0] = 1;                     // unique writer (one-hot row)
        }
        if (!f1 && p && (v1.x | v1.y | v1.z | v1.w)) {
            s_idx[1] = j * 4 + (v1.x ? 0 : (v1.y ? 1 : (v1.z ? 2 : 3)));
            vf[1] = 1;
        }
        if (!f2 && p && (v2.x | v2.y | v2.z | v2.w)) {
            s_idx[2] = j * 4 + (v2.x ? 0 : (v2.y ? 1 : (v2.z ? 2 : 3)));
            vf[2] = 1;
        }
        if (!f3 && p && (v3.x | v3.y | v3.z | v3.w)) {
            s_idx[3] = j * 4 + (v3.x ? 0 : (v3.y ? 1 : (v3.z ? 2 : 3)));
            vf[3] = 1;
        }
    }
    __syncthreads();   // BAR drains STS: s_idx visible below
    if (threadIdx.x < ROWS_PB) {
        const int idx = s_idx[threadIdx.x];
        g_idx[t0 + threadIdx.x] = idx;
        atomicAdd(&g_cnt[idx >> 4], 1);    // fused histogram
    }
}

// ---------------- K2: 1024-thread counting sort (hierarchical scan) ----------------
__global__ __launch_bounds__(1024)
void sort_kernel() {
    __shared__ int s_off[NBUCKPAD];
    __shared__ int s_wsum[32];
    const int tid  = threadIdx.x;
    const int warp = tid >> 5;
    const int lane = tid & 31;

    // 2 buckets per thread; load counts + zero for next call
    const int b2 = tid * 2;
    int2 c = *reinterpret_cast<const int2*>(&g_cnt[b2]);
    *reinterpret_cast<int2*>(&g_cnt[b2]) = make_int2(0, 0);

    const int tsum = c.x + c.y;
    int incl = tsum;
    #pragma unroll
    for (int o = 1; o < 32; o <<= 1) {
        int n = __shfl_up_sync(0xffffffffu, incl, o);
        if (lane >= o) incl += n;
    }
    if (lane == 31) s_wsum[warp] = incl;
    __syncthreads();
    if (warp == 0) {                       // scan the 32 warp sums
        int wsv = s_wsum[lane];
        int wincl = wsv;
        #pragma unroll
        for (int o = 1; o < 32; o <<= 1) {
            int n = __shfl_up_sync(0xffffffffu, wincl, o);
            if (lane >= o) wincl += n;
        }
        s_wsum[lane] = wincl - wsv;        // exclusive warp base
    }
    __syncthreads();
    const int tbase = s_wsum[warp] + (incl - tsum);
    s_off[b2]     = tbase;
    s_off[b2 + 1] = tbase + c.x;
    __syncthreads();

    // scatter 4096 tokens via smem atomics (~2 per bucket)
    #pragma unroll
    for (int k = 0; k < TOKENS / 1024; k++) {
        const int tt  = tid + k * 1024;
        const int idx = g_idx[tt];
        const int pos = atomicAdd(&s_off[idx >> 4], 1);
        g_order[pos] = tt;
        g_sidx[pos]  = idx;
    }
}

// ---------------- K3: warp-coalesced gather, preload-16 + LSQ + transpose ----------------
// grid = (TOKENS/GROUP=128, DIM/128=8); block = 256 (8 warps).
__global__ __launch_bounds__(NTHREADS, 8)
void gather_lsq_kernel(const float* __restrict__ w,
                       const float* __restrict__ alpha,
                       float* __restrict__ out) {
    __shared__ int   s_tok[GROUP];
    __shared__ int   s_ix[GROUP];
    __shared__ float tile[32][33];

    const int tid  = threadIdx.x;
    const int warp = tid >> 5;
    const int lane = tid & 31;
    const int gbase  = blockIdx.x * GROUP;
    const int dbase0 = blockIdx.y * 128;

    if (tid < GROUP) {
        s_tok[tid] = g_order[gbase + tid];
        s_ix[tid]  = g_sidx[gbase + tid];
    }
    __syncthreads();

    const float a = __ldg(alpha);
    const int   myidx = s_ix[lane];        // lane <-> sorted token (load phase)
    const bool  pad   = (myidx == 0);

    // Preload all 16 gathered values: MLP=16 per thread.
    float wv[16];
    #pragma unroll
    for (int c = 0; c < 4; c++)
        #pragma unroll
        for (int r = 0; r < 4; r++)
            wv[c * 4 + r] =
                __ldg(w + (size_t)(dbase0 + c * 32 + warp * 4 + r) * VOCAB + myidx);

    #pragma unroll
    for (int c = 0; c < 4; c++) {
        const int dbase = dbase0 + c * 32;
        #pragma unroll
        for (int r = 0; r < 4; r++) {
            float q = pad ? 0.0f
                          : rintf(fminf(fmaxf(wv[c * 4 + r] / a, -8.0f), 7.0f)) * a;
            tile[warp * 4 + r][lane] = q;
        }
        __syncthreads();
        #pragma unroll
        for (int r = 0; r < 4; r++) {
            const int tl = warp * 4 + r;
            const int t  = s_tok[tl];
            out[(size_t)t * DIM + dbase + lane] = tile[lane][tl];
        }
        __syncthreads();
    }
}

extern "C" void kernel_launch(void* const* d_in, const int* in_sizes, int n_in,
                              void* d_out, int out_size) {
    const float* x     = (const float*)d_in[0];
    const float* w     = (const float*)d_in[1];
    const float* alpha = (const float*)d_in[2];
    float* out = (float*)d_out;

    find_idx_kernel<<<TOKENS / ROWS_PB, NTHREADS>>>(x);
    sort_kernel<<<1, 1024>>>();
    dim3 grid(TOKENS / GROUP, DIM / 128);
    gather_lsq_kernel<<<grid, NTHREADS>>>(w, alpha, out);
}

// round 17
// speedup vs baseline: 1.0479x; 1.0035x over previous
#include <cuda_runtime.h>
#include <cstdint>

// EmbeddingLSQ: out[t, d] = (idx[t]==0) ? 0 : round(clamp(W[d, idx[t]]/a, -8, 7))*a
// where idx[t] = argmax_v x[t, v]  (x is one-hot float32).
//
// Pipeline (3 kernels, single stream):
//  K1 find_idx : QUAD-ROW early-exit scan (grid=1024, one resident wave; all
//                4096 rows progress concurrently -> minimal detection
//                overshoot; measured 49.0us/282MB). __ldcs streaming loads.
//  K2 sort     : 1024-thread counting sort, hierarchical warp-shfl scan,
//                re-zeroes g_cnt for the next call.
//  K3 gather   : warp-coalesced gather over sorted tokens, 2-stage pipelined
//                chunks (R13's measured-best form), smem transpose,
//                coalesced writes.
//
// Cross-call state: g_cnt zero at entry every call (zero-init first call,
// re-zeroed by K2) -> graph replays do identical work.

#define VOCAB    32000
#define DIM      1024
#define TOKENS   4096
#define NTHREADS 256
#define U4_PER_ROW (VOCAB / 4)          // 8000 uint4 per row
#define NBUCKETS 2000                   // idx>>4 buckets (64B vocab span)
#define NBUCKPAD 2048
#define GROUP    32                     // tokens per gather group
#define ROWS_PB  4                      // rows per block in K1

__device__ int g_idx[TOKENS];
__device__ __align__(16) int g_cnt[NBUCKPAD];   // zero at entry of every call
__device__ int g_order[TOKENS];
__device__ int g_sidx[TOKENS];

// ---------------- K1: quad-row early-exit scan + fused histogram ----------------
__global__ __launch_bounds__(NTHREADS, 8)
void find_idx_kernel(const float* __restrict__ x) {
    const int t0 = blockIdx.x * ROWS_PB;
    __shared__ int s_idx[ROWS_PB];
    __shared__ int s_flag[ROWS_PB];
    if (threadIdx.x < ROWS_PB) { s_idx[threadIdx.x] = 0; s_flag[threadIdx.x] = 0; }
    __syncthreads();

    const uint4* __restrict__ row0 = reinterpret_cast<const uint4*>(x + (size_t)(t0 + 0) * VOCAB);
    const uint4* __restrict__ row1 = reinterpret_cast<const uint4*>(x + (size_t)(t0 + 1) * VOCAB);
    const uint4* __restrict__ row2 = reinterpret_cast<const uint4*>(x + (size_t)(t0 + 2) * VOCAB);
    const uint4* __restrict__ row3 = reinterpret_cast<const uint4*>(x + (size_t)(t0 + 3) * VOCAB);
    volatile int* vf = s_flag;

    // batch-1 per row, 4 rows interleaved: MLP/thread=4, per-row in-flight=1.
    // __ldcs: x is a single-use stream; evict-first keeps L2 clean.
    for (int base = 0; base < 32; base++) {
        const int f0 = vf[0], f1 = vf[1], f2 = vf[2], f3 = vf[3];
        if (f0 & f1 & f2 & f3) break;
        const int j = threadIdx.x + base * NTHREADS;
        const bool p = (j < U4_PER_ROW);
        uint4 v0, v1, v2, v3;
        if (!f0 && p) v0 = __ldcs(&row0[j]);   // block-uniform row predicates
        if (!f1 && p) v1 = __ldcs(&row1[j]);
        if (!f2 && p) v2 = __ldcs(&row2[j]);
        if (!f3 && p) v3 = __ldcs(&row3[j]);
        if (!f0 && p && (v0.x | v0.y | v0.z | v0.w)) {
            s_idx[0] = j * 4 + (v0.x ? 0 : (v0.y ? 1 : (v0.z ? 2 : 3)));
            vf[0] = 1;                     // unique writer (one-hot row)
        }
        if (!f1 && p && (v1.x | v1.y | v1.z | v1.w)) {
            s_idx[1] = j * 4 + (v1.x ? 0 : (v1.y ? 1 : (v1.z ? 2 : 3)));
            vf[1] = 1;
        }
        if (!f2 && p && (v2.x | v2.y | v2.z | v2.w)) {
            s_idx[2] = j * 4 + (v2.x ? 0 : (v2.y ? 1 : (v2.z ? 2 : 3)));
            vf[2] = 1;
        }
        if (!f3 && p && (v3.x | v3.y | v3.z | v3.w)) {
            s_idx[3] = j * 4 + (v3.x ? 0 : (v3.y ? 1 : (v3.z ? 2 : 3)));
            vf[3] = 1;
        }
    }
    __syncthreads();   // BAR drains STS: s_idx visible below
    if (threadIdx.x < ROWS_PB) {
        const int idx = s_idx[threadIdx.x];
        g_idx[t0 + threadIdx.x] = idx;
        atomicAdd(&g_cnt[idx >> 4], 1);    // fused histogram
    }
}

// ---------------- K2: 1024-thread counting sort (hierarchical scan) ----------------
__global__ __launch_bounds__(1024)
void sort_kernel() {
    __shared__ int s_off[NBUCKPAD];
    __shared__ int s_wsum[32];
    const int tid  = threadIdx.x;
    const int warp = tid >> 5;
    const int lane = tid & 31;

    // 2 buckets per thread; load counts + zero for next call
    const int b2 = tid * 2;
    int2 c = *reinterpret_cast<const int2*>(&g_cnt[b2]);
    *reinterpret_cast<int2*>(&g_cnt[b2]) = make_int2(0, 0);

    const int tsum = c.x + c.y;
    int incl = tsum;
    #pragma unroll
    for (int o = 1; o < 32; o <<= 1) {
        int n = __shfl_up_sync(0xffffffffu, incl, o);
        if (lane >= o) incl += n;
    }
    if (lane == 31) s_wsum[warp] = incl;
    __syncthreads();
    if (warp == 0) {                       // scan the 32 warp sums
        int wsv = s_wsum[lane];
        int wincl = wsv;
        #pragma unroll
        for (int o = 1; o < 32; o <<= 1) {
            int n = __shfl_up_sync(0xffffffffu, wincl, o);
            if (lane >= o) wincl += n;
        }
        s_wsum[lane] = wincl - wsv;        // exclusive warp base
    }
    __syncthreads();
    const int tbase = s_wsum[warp] + (incl - tsum);
    s_off[b2]     = tbase;
    s_off[b2 + 1] = tbase + c.x;
    __syncthreads();

    // scatter 4096 tokens via smem atomics (~2 per bucket)
    #pragma unroll
    for (int k = 0; k < TOKENS / 1024; k++) {
        const int tt  = tid + k * 1024;
        const int idx = g_idx[tt];
        const int pos = atomicAdd(&s_off[idx >> 4], 1);
        g_order[pos] = tt;
        g_sidx[pos]  = idx;
    }
}

// ---------------- K3: warp-coalesced pipelined gather + LSQ + transpose ----------------
// grid = (TOKENS/GROUP=128, DIM/128=8); block = 256 (8 warps).
__global__ __launch_bounds__(NTHREADS, 8)
void gather_lsq_kernel(const float* __restrict__ w,
                       const float* __restrict__ alpha,
                       float* __restrict__ out) {
    __shared__ int   s_tok[GROUP];
    __shared__ int   s_ix[GROUP];
    __shared__ float tile[32][33];

    const int tid  = threadIdx.x;
    const int warp = tid >> 5;
    const int lane = tid & 31;
    const int gbase  = blockIdx.x * GROUP;
    const int dbase0 = blockIdx.y * 128;

    if (tid < GROUP) {
        s_tok[tid] = g_order[gbase + tid];
        s_ix[tid]  = g_sidx[gbase + tid];
    }
    __syncthreads();

    const float a = __ldg(alpha);
    const int   myidx = s_ix[lane];        // lane <-> sorted token (load phase)
    const bool  pad   = (myidx == 0);

    // 2-stage software pipeline over 4 chunks of 32 d (R13 measured-best):
    // chunk c+1 loads issued before chunk c's transpose/writes.
    float wv[4];
    #pragma unroll
    for (int r = 0; r < 4; r++)
        wv[r] = __ldg(w + (size_t)(dbase0 + warp * 4 + r) * VOCAB + myidx);

    #pragma unroll
    for (int c = 0; c < 4; c++) {
        float nv[4];
        if (c < 3) {
            const int dnext = dbase0 + (c + 1) * 32;
            #pragma unroll
            for (int r = 0; r < 4; r++)
                nv[r] = __ldg(w + (size_t)(dnext + warp * 4 + r) * VOCAB + myidx);
        }
        const int dbase = dbase0 + c * 32;
        #pragma unroll
        for (int r = 0; r < 4; r++) {
            float q = pad ? 0.0f
                          : rintf(fminf(fmaxf(wv[r] / a, -8.0f), 7.0f)) * a;
            tile[warp * 4 + r][lane] = q;
        }
        __syncthreads();
        #pragma unroll
        for (int r = 0; r < 4; r++) {
            const int tl = warp * 4 + r;
            const int t  = s_tok[tl];
            out[(size_t)t * DIM + dbase + lane] = tile[lane][tl];
        }
        __syncthreads();
        #pragma unroll
        for (int r = 0; r < 4; r++) wv[r] = nv[r];
    }
}

extern "C" void kernel_launch(void* const* d_in, const int* in_sizes, int n_in,
                              void* d_out, int out_size) {
    const float* x     = (const float*)d_in[0];
    const float* w     = (const float*)d_in[1];
    const float* alpha = (const float*)d_in[2];
    float* out = (float*)d_out;

    find_idx_kernel<<<TOKENS / ROWS_PB, NTHREADS>>>(x);
    sort_kernel<<<1, 1024>>>();
    dim3 grid(TOKENS / GROUP, DIM / 128);
    gather_lsq_kernel<<<grid, NTHREADS>>>(w, alpha, out);
}